// round 2
// baseline (speedup 1.0000x reference)
#include <cuda_runtime.h>
#include <cstdint>

#define ULL unsigned long long

// ---------------- problem constants ----------------
#define Bb    128
#define Tt    512
#define NOBS  256
#define Hh    512
#define G4    2048            // 4*H
#define NACT  32
#define MTOT  (Bb * Tt)       // 65536

// ---------------- device scratch (static __device__ arrays are the blessed scratch) ----
__device__ float g_xg[(size_t)MTOT * G4];   // 512 MB : obs @ Wx, (B*T, 4H)
__device__ float g_ys[(size_t)MTOT * Hh];   // 128 MB : LSTM hidden per step (B,T,H)
__device__ float g_a1[(size_t)MTOT * Hh];   // 128 MB
__device__ float g_a2[(size_t)MTOT * Hh];   // 128 MB
__device__ float g_hbuf[2][Bb * Hh];        // double-buffered h
__device__ unsigned g_count = 0;
__device__ volatile unsigned g_phase = 0;

// ---------------- f32x2 helpers ----------------
__device__ __forceinline__ ULL ffma2(ULL a, ULL b, ULL c) {
    ULL d;
    asm("fma.rn.f32x2 %0, %1, %2, %3;" : "=l"(d) : "l"(a), "l"(b), "l"(c));
    return d;
}
__device__ __forceinline__ ULL pack2(float lo, float hi) {
    ULL d;
    asm("mov.b64 %0, {%1, %2};" : "=l"(d) : "f"(lo), "f"(hi));
    return d;
}
__device__ __forceinline__ void unpack2(ULL v, float& lo, float& hi) {
    asm("mov.b64 {%0, %1}, %2;" : "=f"(lo), "=f"(hi) : "l"(v));
}

__device__ __forceinline__ float sigmoidf_(float x) {
    return 1.0f / (1.0f + expf(-x));
}

// ---------------- hand-rolled grid barrier (all CTAs co-resident: grid=128 <= 148 SMs) --
__device__ __forceinline__ void grid_sync(int nb) {
    __syncthreads();
    if (threadIdx.x == 0) {
        unsigned ph = g_phase;           // read phase BEFORE arriving
        __threadfence();                 // make this CTA's h/ys writes visible
        if (atomicAdd(&g_count, 1u) == (unsigned)nb - 1u) {
            g_count = 0u;
            __threadfence();
            g_phase = ph + 1u;
        } else {
            while (g_phase == ph) { __nanosleep(32); }
        }
    }
    __syncthreads();
}

// =====================================================================================
// Generic fused GEMM: C = act(A[M,K] @ W[K,N] + bias)
// ACT: 0 = none (no bias), 1 = bias+relu, 2 = bias+tanh+action-scale
// f32x2 inner loop: accumulators packed over row pairs; W dup-packed (w,w) in smem.
// =====================================================================================
template <int BM, int BN, int BK, int TM, int TN, int ACT>
__global__ __launch_bounds__(256)
void gemm_act(const float* __restrict__ A, const float* __restrict__ W,
              const float* __restrict__ bias, float* __restrict__ C,
              int M, int N, int K,
              const float* __restrict__ amin, const float* __restrict__ amax)
{
    static_assert((BM / TM) * (BN / TN) == 256, "thread count");
    static_assert(TN == 4, "epilogue assumes float4");
    static_assert((TM & 1) == 0, "row pairing");

    __shared__ __align__(16) float Ast[BK][BM + 8];   // transposed A tile
    __shared__ __align__(16) ULL   Wd[BK][BN];        // dup-packed W tile

    const int tid = threadIdx.x;
    const int tx  = tid % (BN / TN);
    const int ty  = tid / (BN / TN);
    const int m0  = blockIdx.y * BM;
    const int n0  = blockIdx.x * BN;
    const int r0  = ty * TM;
    const int c0  = tx * TN;

    ULL acc[TM / 2][TN];
    #pragma unroll
    for (int i = 0; i < TM / 2; i++)
        #pragma unroll
        for (int j = 0; j < TN; j++) acc[i][j] = 0ULL;

    for (int kc = 0; kc < K; kc += BK) {
        // ---- fill A tile (transposed) ----
        #pragma unroll
        for (int q = 0; q < (BM * BK) / (256 * 4); q++) {
            int idx = tid + 256 * q;
            int r   = idx / (BK / 4);
            int kq  = idx % (BK / 4);
            float4 v = *reinterpret_cast<const float4*>(
                &A[(size_t)(m0 + r) * K + kc + kq * 4]);
            Ast[kq * 4 + 0][r] = v.x;
            Ast[kq * 4 + 1][r] = v.y;
            Ast[kq * 4 + 2][r] = v.z;
            Ast[kq * 4 + 3][r] = v.w;
        }
        // ---- fill W tile, dup-packed ----
        #pragma unroll
        for (int q = 0; q < (BK * BN) / 256; q++) {
            int idx = tid + 256 * q;
            int k   = idx / BN;
            int c   = idx % BN;
            float w = W[(size_t)(kc + k) * N + n0 + c];
            Wd[k][c] = pack2(w, w);
        }
        __syncthreads();

        #pragma unroll
        for (int kk = 0; kk < BK; kk++) {
            ULL a[TM / 2];
            #pragma unroll
            for (int i = 0; i < TM / 2; i++)
                a[i] = *reinterpret_cast<const ULL*>(&Ast[kk][r0 + 2 * i]);
            ULL w[TN];
            #pragma unroll
            for (int j = 0; j < TN; j++) w[j] = Wd[kk][c0 + j];
            #pragma unroll
            for (int i = 0; i < TM / 2; i++)
                #pragma unroll
                for (int j = 0; j < TN; j++)
                    acc[i][j] = ffma2(a[i], w[j], acc[i][j]);
        }
        __syncthreads();
    }

    // ---- epilogue ----
    float bc[TN], sA[TN], sB[TN];
    #pragma unroll
    for (int j = 0; j < TN; j++) { bc[j] = 0.f; sA[j] = 0.f; sB[j] = 0.f; }
    if constexpr (ACT >= 1) {
        #pragma unroll
        for (int j = 0; j < TN; j++) bc[j] = bias[n0 + c0 + j];
    }
    if constexpr (ACT == 2) {
        #pragma unroll
        for (int j = 0; j < TN; j++) {
            float lo = amin[n0 + c0 + j], hi = amax[n0 + c0 + j];
            sA[j] = 0.5f * (hi - lo);
            sB[j] = 0.5f * (hi + lo);
        }
    }

    #pragma unroll
    for (int i = 0; i < TM / 2; i++) {
        float vlo[TN], vhi[TN];
        #pragma unroll
        for (int j = 0; j < TN; j++) unpack2(acc[i][j], vlo[j], vhi[j]);
        int row = m0 + r0 + 2 * i;
        #pragma unroll
        for (int h = 0; h < 2; h++) {
            float* v = (h == 0) ? vlo : vhi;
            float4 o;
            float ov[4];
            #pragma unroll
            for (int j = 0; j < TN; j++) {
                float x = v[j];
                if constexpr (ACT == 1) x = fmaxf(x + bc[j], 0.0f);
                if constexpr (ACT == 2) { x = tanhf(x + bc[j]); x = x * sA[j] + sB[j]; }
                ov[j] = x;
            }
            o.x = ov[0]; o.y = ov[1]; o.z = ov[2]; o.w = ov[3];
            *reinterpret_cast<float4*>(&C[(size_t)(row + h) * N + n0 + c0]) = o;
        }
    }
}

// =====================================================================================
// Persistent LSTM scan: 128 CTAs, CTA cb owns h-columns [cb*4, cb*4+4).
// Per step: z[:, own 16 cols] = xg_t + h @ Wh_slice + b  -> gates -> c,h update.
// Wh slice dup-packed resident in smem for all 512 steps. One grid barrier per step.
// =====================================================================================
// dynamic smem layout (bytes):
//   Wsm  [512][16] ULL   : 65536
//   Ast  [32][136] float : 17408   (transposed h-chunk, pad 136)
//   zsm  [128][17] float : 8704
//   csm  [128][4]  float : 2048
//   bsm  [16]      float : 64
#define SCAN_SMEM (65536 + 17408 + 8704 + 2048 + 64)

__global__ __launch_bounds__(256, 1)
void scan_kernel(const float* __restrict__ xg, const float* __restrict__ Wh,
                 const float* __restrict__ b,  const float* __restrict__ h0,
                 const float* __restrict__ c0,
                 float* __restrict__ ys, float* __restrict__ hT,
                 float* __restrict__ cT, int nblocks)
{
    extern __shared__ __align__(16) char smraw[];
    ULL   (*Wsm)[16]  = reinterpret_cast<ULL(*)[16]>(smraw);
    float (*Ast)[136] = reinterpret_cast<float(*)[136]>(smraw + 65536);
    float (*zsm)[17]  = reinterpret_cast<float(*)[17]>(smraw + 65536 + 17408);
    float (*csm)[4]   = reinterpret_cast<float(*)[4]>(smraw + 65536 + 17408 + 8704);
    float *bsm        = reinterpret_cast<float*>(smraw + 65536 + 17408 + 8704 + 2048);

    const int tid = threadIdx.x;
    const int cb  = blockIdx.x;
    const int j0  = cb * 4;          // owned h-column base
    const int cg  = tid & 3;         // gate index == column-group
    const int rp  = tid >> 2;        // 0..63 row pair
    const int ra  = 2 * rp, rb = 2 * rp + 1;

    // resident weights: Wsm[k][c], c = gate*4 + jj  -> z-col = gate*512 + j0 + jj
    for (int idx = tid; idx < 512 * 16; idx += 256) {
        int k = idx >> 4, c = idx & 15;
        int zcol = (c >> 2) * 512 + j0 + (c & 3);
        float w = Wh[(size_t)k * G4 + zcol];
        Wsm[k][c] = pack2(w, w);
    }
    if (tid < 16) bsm[tid] = b[(tid >> 2) * 512 + j0 + (tid & 3)];
    for (int idx = tid; idx < 512; idx += 256) {
        int r = idx >> 2, jj = idx & 3;
        csm[r][jj] = c0[r * Hh + j0 + jj];
    }
    // init h double-buffer slot 0 with h0 (grid-strided)
    for (int idx = cb * 256 + tid; idx < Bb * Hh; idx += nblocks * 256)
        g_hbuf[0][idx] = h0[idx];

    grid_sync(nblocks);

    for (int t = 0; t < Tt; t++) {
        const float* hsrc = g_hbuf[t & 1];
        float*       hdst = g_hbuf[(t + 1) & 1];

        // acc init: z = xg_t + b   (acc packed over row pair (ra,rb))
        ULL acc0, acc1, acc2v, acc3;
        {
            const float4 xa = *reinterpret_cast<const float4*>(
                &xg[(size_t)(ra * Tt + t) * G4 + cg * 512 + j0]);
            const float4 xb = *reinterpret_cast<const float4*>(
                &xg[(size_t)(rb * Tt + t) * G4 + cg * 512 + j0]);
            float b0 = bsm[cg * 4 + 0], b1 = bsm[cg * 4 + 1];
            float b2 = bsm[cg * 4 + 2], b3 = bsm[cg * 4 + 3];
            acc0  = pack2(xa.x + b0, xb.x + b0);
            acc1  = pack2(xa.y + b1, xb.y + b1);
            acc2v = pack2(xa.z + b2, xb.z + b2);
            acc3  = pack2(xa.w + b3, xb.w + b3);
        }

        // K loop over h (K = 512), 32-wide chunks staged in smem (transposed)
        for (int kc = 0; kc < Hh; kc += 32) {
            #pragma unroll
            for (int q = 0; q < 4; q++) {
                int idx = tid + 256 * q;
                int r = idx >> 3, kq = idx & 7;
                // .cg: L1 is not coherent across the software grid barrier
                float4 v = __ldcg(reinterpret_cast<const float4*>(
                    &hsrc[r * Hh + kc + kq * 4]));
                Ast[kq * 4 + 0][r] = v.x;
                Ast[kq * 4 + 1][r] = v.y;
                Ast[kq * 4 + 2][r] = v.z;
                Ast[kq * 4 + 3][r] = v.w;
            }
            __syncthreads();
            #pragma unroll
            for (int kk = 0; kk < 32; kk++) {
                ULL a  = *reinterpret_cast<const ULL*>(&Ast[kk][ra]);
                ULL w0 = Wsm[kc + kk][cg * 4 + 0];
                ULL w1 = Wsm[kc + kk][cg * 4 + 1];
                ULL w2 = Wsm[kc + kk][cg * 4 + 2];
                ULL w3 = Wsm[kc + kk][cg * 4 + 3];
                acc0  = ffma2(a, w0, acc0);
                acc1  = ffma2(a, w1, acc1);
                acc2v = ffma2(a, w2, acc2v);
                acc3  = ffma2(a, w3, acc3);
            }
            __syncthreads();
        }

        // stash z into smem for the gate update
        {
            float lo, hi;
            unpack2(acc0,  lo, hi); zsm[ra][cg * 4 + 0] = lo; zsm[rb][cg * 4 + 0] = hi;
            unpack2(acc1,  lo, hi); zsm[ra][cg * 4 + 1] = lo; zsm[rb][cg * 4 + 1] = hi;
            unpack2(acc2v, lo, hi); zsm[ra][cg * 4 + 2] = lo; zsm[rb][cg * 4 + 2] = hi;
            unpack2(acc3,  lo, hi); zsm[ra][cg * 4 + 3] = lo; zsm[rb][cg * 4 + 3] = hi;
        }
        __syncthreads();

        // gate update: 128 rows x 4 owned cols = 512 elems, 2 per thread
        #pragma unroll
        for (int s = 0; s < 2; s++) {
            int idx = tid + 256 * s;
            int r = idx >> 2, jj = idx & 3;
            float zi = zsm[r][0 + jj];
            float zf = zsm[r][4 + jj];
            float zg = zsm[r][8 + jj];
            float zo = zsm[r][12 + jj];
            float cc = csm[r][jj];
            float cn = sigmoidf_(zf) * cc + sigmoidf_(zi) * tanhf(zg);
            float hn = sigmoidf_(zo) * tanhf(cn);
            csm[r][jj] = cn;
            hdst[r * Hh + j0 + jj] = hn;
            ys[(size_t)(r * Tt + t) * Hh + j0 + jj] = hn;
            if (t == Tt - 1) hT[r * Hh + j0 + jj] = hn;
        }

        grid_sync(nblocks);
    }

    // final c
    for (int idx = tid; idx < 512; idx += 256) {
        int r = idx >> 2, jj = idx & 3;
        cT[r * Hh + j0 + jj] = csm[r][jj];
    }
}

// =====================================================================================
extern "C" void kernel_launch(void* const* d_in, const int* in_sizes, int n_in,
                              void* d_out, int out_size)
{
    const float* obs  = (const float*)d_in[0];
    const float* h0   = (const float*)d_in[1];
    const float* c0   = (const float*)d_in[2];
    const float* Wx   = (const float*)d_in[3];
    const float* Wh   = (const float*)d_in[4];
    const float* b    = (const float*)d_in[5];
    const float* W1   = (const float*)d_in[6];
    const float* b1   = (const float*)d_in[7];
    const float* W2   = (const float*)d_in[8];
    const float* b2   = (const float*)d_in[9];
    const float* Wo   = (const float*)d_in[10];
    const float* bo   = (const float*)d_in[11];
    const float* amin = (const float*)d_in[12];
    const float* amax = (const float*)d_in[13];

    float* out        = (float*)d_out;
    float* out_action = out;                                  // (B,T,NACT)
    float* out_h      = out + (size_t)MTOT * NACT;            // (B,H)
    float* out_c      = out_h + (size_t)Bb * Hh;              // (B,H)

    float *p_xg, *p_ys, *p_a1, *p_a2;
    cudaGetSymbolAddress((void**)&p_xg, g_xg);
    cudaGetSymbolAddress((void**)&p_ys, g_ys);
    cudaGetSymbolAddress((void**)&p_a1, g_a1);
    cudaGetSymbolAddress((void**)&p_a2, g_a2);

    cudaFuncSetAttribute(scan_kernel,
                         cudaFuncAttributeMaxDynamicSharedMemorySize, SCAN_SMEM);

    // 1) xg = obs @ Wx          (65536 x 2048, K=256)
    {
        dim3 grid(G4 / 64, MTOT / 128);
        gemm_act<128, 64, 16, 8, 4, 0><<<grid, 256>>>(
            obs, Wx, nullptr, p_xg, MTOT, G4, NOBS, nullptr, nullptr);
    }
    // 2) LSTM scan (persistent, 128 CTAs)
    scan_kernel<<<128, 256, SCAN_SMEM>>>(p_xg, Wh, b, h0, c0,
                                         p_ys, out_h, out_c, 128);
    // 3) a1 = relu(ys @ W1 + b1)
    {
        dim3 grid(Hh / 64, MTOT / 128);
        gemm_act<128, 64, 16, 8, 4, 1><<<grid, 256>>>(
            p_ys, W1, b1, p_a1, MTOT, Hh, Hh, nullptr, nullptr);
    }
    // 4) a2 = relu(a1 @ W2 + b2)
    {
        dim3 grid(Hh / 64, MTOT / 128);
        gemm_act<128, 64, 16, 8, 4, 1><<<grid, 256>>>(
            p_a1, W2, b2, p_a2, MTOT, Hh, Hh, nullptr, nullptr);
    }
    // 5) action = 0.5*(tanh(a2 @ Wo + bo)*(amax-amin) + (amax+amin))
    {
        dim3 grid(NACT / 32, MTOT / 128);
        gemm_act<128, 32, 16, 4, 4, 2><<<grid, 256>>>(
            p_a2, Wo, bo, out_action, MTOT, NACT, Hh, amin, amax);
    }
    (void)in_sizes; (void)n_in; (void)out_size;
}

// round 3
// speedup vs baseline: 1.8163x; 1.8163x over previous
#include <cuda_runtime.h>
#include <cstdint>

typedef unsigned long long ULL;

// ---------------- problem constants ----------------
#define Bb    128
#define Tt    512
#define NOBS  256
#define Hh    512
#define G4    2048            // 4*H
#define NACT  32
#define MTOT  (Bb * Tt)       // 65536

// SW128-style swizzle on a byte offset (bits[4:6] ^= bits[7:9])
#define SWZ(off) ((off) ^ (((off) >> 3) & 0x70u))

// ---------------- device scratch ----------------
__device__ float g_xg[(size_t)MTOT * G4];     // obs @ Wx, (B*T, 4H)
__device__ float g_ys[(size_t)MTOT * Hh];     // LSTM hidden per step (B,T,H)
__device__ float g_a1[(size_t)MTOT * Hh];
__device__ float g_a2[(size_t)MTOT * Hh];
__device__ float g_hT[2][Hh * Bb];            // double-buffered h, TRANSPOSED [H][B]
__device__ unsigned g_count = 0;
__device__ volatile unsigned g_phase = 0;

// ---------------- f32x2 helpers ----------------
__device__ __forceinline__ ULL ffma2(ULL a, ULL b, ULL c) {
    ULL d;
    asm("fma.rn.f32x2 %0, %1, %2, %3;" : "=l"(d) : "l"(a), "l"(b), "l"(c));
    return d;
}
__device__ __forceinline__ ULL pack2(float lo, float hi) {
    ULL d;
    asm("mov.b64 %0, {%1, %2};" : "=l"(d) : "f"(lo), "f"(hi));
    return d;
}
__device__ __forceinline__ void unpack2(ULL v, float& lo, float& hi) {
    asm("mov.b64 {%0, %1}, %2;" : "=f"(lo), "=f"(hi) : "l"(v));
}
__device__ __forceinline__ float sigmoidf_(float x) {
    return 1.0f / (1.0f + expf(-x));
}

// ---------------- grid barrier (all 128 CTAs co-resident) ----------------
__device__ __forceinline__ void grid_sync(int nb) {
    __syncthreads();
    if (threadIdx.x == 0) {
        unsigned ph = g_phase;
        __threadfence();
        if (atomicAdd(&g_count, 1u) == (unsigned)nb - 1u) {
            g_count = 0u;
            __threadfence();
            g_phase = ph + 1u;
        } else {
            while (g_phase == ph) { __nanosleep(32); }
        }
    }
    __syncthreads();
}

// =====================================================================================
// GEMM 128x128x16, per-thread 8x8, all-LDS.128 operand loads, swizzled W tile.
// ACT: 0 = none (no bias), 1 = bias+relu
// =====================================================================================
template <int ACT>
__global__ __launch_bounds__(256)
void gemm128(const float* __restrict__ A, const float* __restrict__ W,
             const float* __restrict__ bias, float* __restrict__ C,
             int M, int N, int K)
{
    __shared__ __align__(16)  float As[16][132];          // transposed A tile (132*4 = 16B mult)
    __shared__ __align__(128) char  WdRaw[16 * 128 * 8];  // dup-packed W, swizzled

    const int tid = threadIdx.x;
    const int tx  = tid & 15;         // n-dir
    const int ty  = tid >> 4;         // m-dir
    const int m0  = blockIdx.y * 128;
    const int n0  = blockIdx.x * 128;
    const int r0  = ty * 8;
    const int c0  = tx * 8;

    ULL acc[4][8];
    #pragma unroll
    for (int i = 0; i < 4; i++)
        #pragma unroll
        for (int j = 0; j < 8; j++) acc[i][j] = 0ULL;

    for (int kc = 0; kc < K; kc += 16) {
        // ---- A tile fill (transposed), 2 float4/thread ----
        #pragma unroll
        for (int q = 0; q < 2; q++) {
            int idx = tid + 256 * q;
            int m   = idx >> 2;
            int kq  = idx & 3;
            float4 v = *reinterpret_cast<const float4*>(
                &A[(size_t)(m0 + m) * K + kc + kq * 4]);
            As[kq * 4 + 0][m] = v.x;
            As[kq * 4 + 1][m] = v.y;
            As[kq * 4 + 2][m] = v.z;
            As[kq * 4 + 3][m] = v.w;
        }
        // ---- W tile fill, dup-packed + swizzled, 4 ULL2/thread ----
        #pragma unroll
        for (int q = 0; q < 4; q++) {
            int f  = tid + 256 * q;
            int k  = f >> 6;
            int cp = f & 63;        // 16B unit index within row (cols 2cp, 2cp+1)
            float2 wv = *reinterpret_cast<const float2*>(
                &W[(size_t)(kc + k) * N + n0 + 2 * cp]);
            ulonglong2 pk;
            pk.x = pack2(wv.x, wv.x);
            pk.y = pack2(wv.y, wv.y);
            unsigned off = (unsigned)(k * 1024 + cp * 16);
            *reinterpret_cast<ulonglong2*>(WdRaw + SWZ(off)) = pk;
        }
        __syncthreads();

        #pragma unroll
        for (int kk = 0; kk < 16; kk++) {
            ulonglong2 a01 = *reinterpret_cast<const ulonglong2*>(&As[kk][r0]);
            ulonglong2 a23 = *reinterpret_cast<const ulonglong2*>(&As[kk][r0 + 4]);
            ULL a[4] = {a01.x, a01.y, a23.x, a23.y};
            ULL w[8];
            #pragma unroll
            for (int q = 0; q < 4; q++) {
                unsigned off = (unsigned)(kk * 1024 + (c0 + 2 * q) * 8);
                ulonglong2 wv = *reinterpret_cast<const ulonglong2*>(WdRaw + SWZ(off));
                w[2 * q]     = wv.x;
                w[2 * q + 1] = wv.y;
            }
            #pragma unroll
            for (int i = 0; i < 4; i++)
                #pragma unroll
                for (int j = 0; j < 8; j++)
                    acc[i][j] = ffma2(a[i], w[j], acc[i][j]);
        }
        __syncthreads();
    }

    // ---- epilogue ----
    float bc[8];
    #pragma unroll
    for (int j = 0; j < 8; j++) bc[j] = 0.0f;
    if constexpr (ACT >= 1) {
        #pragma unroll
        for (int j = 0; j < 8; j++) bc[j] = bias[n0 + c0 + j];
    }

    #pragma unroll
    for (int i = 0; i < 4; i++) {
        float vlo[8], vhi[8];
        #pragma unroll
        for (int j = 0; j < 8; j++) unpack2(acc[i][j], vlo[j], vhi[j]);
        int row = m0 + r0 + 2 * i;
        #pragma unroll
        for (int h = 0; h < 2; h++) {
            float* v = (h == 0) ? vlo : vhi;
            float ov[8];
            #pragma unroll
            for (int j = 0; j < 8; j++) {
                float x = v[j];
                if constexpr (ACT == 1) x = fmaxf(x + bc[j], 0.0f);
                ov[j] = x;
            }
            float4 o0 = {ov[0], ov[1], ov[2], ov[3]};
            float4 o1 = {ov[4], ov[5], ov[6], ov[7]};
            *reinterpret_cast<float4*>(&C[(size_t)(row + h) * N + n0 + c0])     = o0;
            *reinterpret_cast<float4*>(&C[(size_t)(row + h) * N + n0 + c0 + 4]) = o1;
        }
    }
}

// =====================================================================================
// Small GEMM for the final action head (N=32): C = 0.5*(tanh(A@W+b)*(amax-amin)+(amax+amin))
// (kept from round-2 design: BM=128, BN=32, BK=16, TM=4, TN=4)
// =====================================================================================
__global__ __launch_bounds__(256)
void gemm_head(const float* __restrict__ A, const float* __restrict__ W,
               const float* __restrict__ bias, float* __restrict__ C,
               int M, int N, int K,
               const float* __restrict__ amin, const float* __restrict__ amax)
{
    __shared__ __align__(16) float Ast[16][136];
    __shared__ __align__(16) ULL   Wd[16][32];

    const int tid = threadIdx.x;
    const int tx  = tid % 8;
    const int ty  = tid / 8;
    const int m0  = blockIdx.y * 128;
    const int n0  = blockIdx.x * 32;
    const int r0  = ty * 4;
    const int c0  = tx * 4;

    ULL acc[2][4];
    #pragma unroll
    for (int i = 0; i < 2; i++)
        #pragma unroll
        for (int j = 0; j < 4; j++) acc[i][j] = 0ULL;

    for (int kc = 0; kc < K; kc += 16) {
        #pragma unroll
        for (int q = 0; q < 2; q++) {
            int idx = tid + 256 * q;
            int m   = idx >> 2;
            int kq  = idx & 3;
            float4 v = *reinterpret_cast<const float4*>(
                &A[(size_t)(m0 + m) * K + kc + kq * 4]);
            Ast[kq * 4 + 0][m] = v.x;
            Ast[kq * 4 + 1][m] = v.y;
            Ast[kq * 4 + 2][m] = v.z;
            Ast[kq * 4 + 3][m] = v.w;
        }
        #pragma unroll
        for (int q = 0; q < 2; q++) {
            int idx = tid + 256 * q;
            if (idx < 16 * 32) {
                int k = idx >> 5, c = idx & 31;
                float w = W[(size_t)(kc + k) * N + n0 + c];
                Wd[k][c] = pack2(w, w);
            }
        }
        __syncthreads();

        #pragma unroll
        for (int kk = 0; kk < 16; kk++) {
            ULL a[2];
            a[0] = *reinterpret_cast<const ULL*>(&Ast[kk][r0]);
            a[1] = *reinterpret_cast<const ULL*>(&Ast[kk][r0 + 2]);
            ULL w[4];
            #pragma unroll
            for (int j = 0; j < 4; j++) w[j] = Wd[kk][c0 + j];
            #pragma unroll
            for (int i = 0; i < 2; i++)
                #pragma unroll
                for (int j = 0; j < 4; j++)
                    acc[i][j] = ffma2(a[i], w[j], acc[i][j]);
        }
        __syncthreads();
    }

    float bc[4], sA[4], sB[4];
    #pragma unroll
    for (int j = 0; j < 4; j++) {
        bc[j] = bias[n0 + c0 + j];
        float lo = amin[n0 + c0 + j], hi = amax[n0 + c0 + j];
        sA[j] = 0.5f * (hi - lo);
        sB[j] = 0.5f * (hi + lo);
    }

    #pragma unroll
    for (int i = 0; i < 2; i++) {
        float vlo[4], vhi[4];
        #pragma unroll
        for (int j = 0; j < 4; j++) unpack2(acc[i][j], vlo[j], vhi[j]);
        int row = m0 + r0 + 2 * i;
        #pragma unroll
        for (int h = 0; h < 2; h++) {
            float* v = (h == 0) ? vlo : vhi;
            float ov[4];
            #pragma unroll
            for (int j = 0; j < 4; j++) {
                float x = tanhf(v[j] + bc[j]);
                ov[j] = x * sA[j] + sB[j];
            }
            float4 o = {ov[0], ov[1], ov[2], ov[3]};
            *reinterpret_cast<float4*>(&C[(size_t)(row + h) * N + n0 + c0]) = o;
        }
    }
}

// =====================================================================================
// Persistent LSTM scan, 128 CTAs. CTA cb owns h-cols [cb*4, cb*4+4) => 16 z-cols.
// Thread micro-tile: 2 cols x 2 row-pairs (4 rows), 1 LDS.128(a) + 1 LDS.128(w) per 4 ffma2.
// h stored transposed [H][B]; per-32k chunk staged as straight contiguous copy,
// double-buffered. xg prefetched per step, folded in at epilogue.
// =====================================================================================
// dynamic smem: Wsm 512*16 ULL = 65536 | Asm 2*32*128 f = 32768 | zsm 128*18 f = 9216
//               csm 128*4 f = 2048 | bsm 16 f = 64
#define SCAN_SMEM (65536 + 32768 + 9216 + 2048 + 64)

__global__ __launch_bounds__(256, 1)
void scan_kernel(const float* __restrict__ xg, const float* __restrict__ Wh,
                 const float* __restrict__ b,  const float* __restrict__ h0,
                 const float* __restrict__ c0,
                 float* __restrict__ ys, float* __restrict__ hT,
                 float* __restrict__ cT, int nblocks)
{
    extern __shared__ __align__(128) char smraw[];
    ULL   (*Wsm)[16]       = reinterpret_cast<ULL(*)[16]>(smraw);
    float (*Asm)[32][128]  = reinterpret_cast<float(*)[32][128]>(smraw + 65536);
    float (*zsm)[18]       = reinterpret_cast<float(*)[18]>(smraw + 65536 + 32768);
    float (*csm)[4]        = reinterpret_cast<float(*)[4]>(smraw + 65536 + 32768 + 9216);
    float *bsm             = reinterpret_cast<float*>(smraw + 65536 + 32768 + 9216 + 2048);

    const int tid = threadIdx.x;
    const int cb  = blockIdx.x;
    const int j0  = cb * 4;
    const int cp  = tid & 7;          // col-pair (cols 2cp, 2cp+1)
    const int rq  = tid >> 3;         // row-quad (rows 4rq..4rq+3)
    const int cA  = 2 * cp;
    const int cBc = 2 * cp + 1;
    // z-column for local col c: gate = c>>2, jj = c&3
    const int zcA = (cA  >> 2) * Hh + j0 + (cA  & 3);
    const int zcB = (cBc >> 2) * Hh + j0 + (cBc & 3);

    // ---- resident dup-packed Wh slice: Wsm[k][c] ----
    for (int idx = tid; idx < 512 * 16; idx += 256) {
        int k = idx >> 4, c = idx & 15;
        int zcol = (c >> 2) * Hh + j0 + (c & 3);
        float w = Wh[(size_t)k * G4 + zcol];
        Wsm[k][c] = pack2(w, w);
    }
    if (tid < 16) bsm[tid] = b[(tid >> 2) * Hh + j0 + (tid & 3)];
    for (int idx = tid; idx < 512; idx += 256) {
        int r = idx >> 2, jj = idx & 3;
        csm[r][jj] = c0[r * Hh + j0 + jj];
    }
    // ---- init transposed h buffer slot 0 ----
    for (int idx = cb * 256 + tid; idx < Hh * Bb; idx += nblocks * 256) {
        int j = idx >> 7, r = idx & 127;
        g_hT[0][idx] = h0[r * Hh + j];
    }
    grid_sync(nblocks);

    for (int t = 0; t < Tt; t++) {
        const float* hs = g_hT[t & 1];
        float*       hd = g_hT[(t + 1) & 1];

        // ---- prefetch xg for this step (DRAM latency hides under K loop) ----
        float xv[4][2];
        #pragma unroll
        for (int rr = 0; rr < 4; rr++) {
            size_t base = ((size_t)(4 * rq + rr) * Tt + t) * G4;
            xv[rr][0] = __ldg(&xg[base + zcA]);
            xv[rr][1] = __ldg(&xg[base + zcB]);
        }

        // ---- stage chunk 0 (contiguous copy) ----
        {
            float4 v[4];
            #pragma unroll
            for (int q = 0; q < 4; q++)
                v[q] = __ldcg(reinterpret_cast<const float4*>(hs) + tid + 256 * q);
            #pragma unroll
            for (int q = 0; q < 4; q++)
                reinterpret_cast<float4*>(&Asm[0][0][0])[tid + 256 * q] = v[q];
        }
        __syncthreads();

        ULL acc00 = 0, acc01 = 0, acc10 = 0, acc11 = 0;

        for (int kc = 0; kc < 16; kc++) {
            const int cur = kc & 1;
            float4 v[4];
            if (kc < 15) {
                const float4* src = reinterpret_cast<const float4*>(hs + (kc + 1) * 32 * 128);
                #pragma unroll
                for (int q = 0; q < 4; q++)
                    v[q] = __ldcg(src + tid + 256 * q);
            }
            #pragma unroll
            for (int kk = 0; kk < 32; kk++) {
                ulonglong2 a = *reinterpret_cast<const ulonglong2*>(&Asm[cur][kk][4 * rq]);
                ulonglong2 w = *reinterpret_cast<const ulonglong2*>(&Wsm[kc * 32 + kk][cA]);
                acc00 = ffma2(a.x, w.x, acc00);
                acc01 = ffma2(a.x, w.y, acc01);
                acc10 = ffma2(a.y, w.x, acc10);
                acc11 = ffma2(a.y, w.y, acc11);
            }
            if (kc < 15) {
                #pragma unroll
                for (int q = 0; q < 4; q++)
                    reinterpret_cast<float4*>(&Asm[cur ^ 1][0][0])[tid + 256 * q] = v[q];
            }
            __syncthreads();
        }

        // ---- stash z = acc + xg + bias ----
        {
            float bA = bsm[cA], bB = bsm[cBc];
            float lo, hi;
            unpack2(acc00, lo, hi);
            zsm[4 * rq + 0][cA]  = lo + xv[0][0] + bA;
            zsm[4 * rq + 1][cA]  = hi + xv[1][0] + bA;
            unpack2(acc01, lo, hi);
            zsm[4 * rq + 0][cBc] = lo + xv[0][1] + bB;
            zsm[4 * rq + 1][cBc] = hi + xv[1][1] + bB;
            unpack2(acc10, lo, hi);
            zsm[4 * rq + 2][cA]  = lo + xv[2][0] + bA;
            zsm[4 * rq + 3][cA]  = hi + xv[3][0] + bA;
            unpack2(acc11, lo, hi);
            zsm[4 * rq + 2][cBc] = lo + xv[2][1] + bB;
            zsm[4 * rq + 3][cBc] = hi + xv[3][1] + bB;
        }
        __syncthreads();

        // ---- gate update: 512 elems, 2 per thread ----
        #pragma unroll
        for (int s = 0; s < 2; s++) {
            int idx = tid + 256 * s;
            int r = idx >> 2, jj = idx & 3;
            float zi = zsm[r][0  + jj];
            float zf = zsm[r][4  + jj];
            float zg = zsm[r][8  + jj];
            float zo = zsm[r][12 + jj];
            float cc = csm[r][jj];
            float cn = sigmoidf_(zf) * cc + sigmoidf_(zi) * tanhf(zg);
            float hn = sigmoidf_(zo) * tanhf(cn);
            csm[r][jj] = cn;
            hd[(j0 + jj) * Bb + r] = hn;
            ys[((size_t)r * Tt + t) * Hh + j0 + jj] = hn;
            if (t == Tt - 1) hT[r * Hh + j0 + jj] = hn;
        }

        grid_sync(nblocks);
    }

    for (int idx = tid; idx < 512; idx += 256) {
        int r = idx >> 2, jj = idx & 3;
        cT[r * Hh + j0 + jj] = csm[r][jj];
    }
}

// =====================================================================================
extern "C" void kernel_launch(void* const* d_in, const int* in_sizes, int n_in,
                              void* d_out, int out_size)
{
    const float* obs  = (const float*)d_in[0];
    const float* h0   = (const float*)d_in[1];
    const float* c0   = (const float*)d_in[2];
    const float* Wx   = (const float*)d_in[3];
    const float* Wh   = (const float*)d_in[4];
    const float* b    = (const float*)d_in[5];
    const float* W1   = (const float*)d_in[6];
    const float* b1   = (const float*)d_in[7];
    const float* W2   = (const float*)d_in[8];
    const float* b2   = (const float*)d_in[9];
    const float* Wo   = (const float*)d_in[10];
    const float* bo   = (const float*)d_in[11];
    const float* amin = (const float*)d_in[12];
    const float* amax = (const float*)d_in[13];

    float* out        = (float*)d_out;
    float* out_action = out;
    float* out_h      = out + (size_t)MTOT * NACT;
    float* out_c      = out_h + (size_t)Bb * Hh;

    float *p_xg, *p_ys, *p_a1, *p_a2;
    cudaGetSymbolAddress((void**)&p_xg, g_xg);
    cudaGetSymbolAddress((void**)&p_ys, g_ys);
    cudaGetSymbolAddress((void**)&p_a1, g_a1);
    cudaGetSymbolAddress((void**)&p_a2, g_a2);

    cudaFuncSetAttribute(scan_kernel,
                         cudaFuncAttributeMaxDynamicSharedMemorySize, SCAN_SMEM);

    // 1) xg = obs @ Wx          (65536 x 2048, K=256)
    {
        dim3 grid(G4 / 128, MTOT / 128);
        gemm128<0><<<grid, 256>>>(obs, Wx, nullptr, p_xg, MTOT, G4, NOBS);
    }
    // 2) LSTM scan (persistent, 128 CTAs)
    scan_kernel<<<128, 256, SCAN_SMEM>>>(p_xg, Wh, b, h0, c0,
                                         p_ys, out_h, out_c, 128);
    // 3) a1 = relu(ys @ W1 + b1)
    {
        dim3 grid(Hh / 128, MTOT / 128);
        gemm128<1><<<grid, 256>>>(p_ys, W1, b1, p_a1, MTOT, Hh, Hh);
    }
    // 4) a2 = relu(a1 @ W2 + b2)
    {
        dim3 grid(Hh / 128, MTOT / 128);
        gemm128<1><<<grid, 256>>>(p_a1, W2, b2, p_a2, MTOT, Hh, Hh);
    }
    // 5) action head
    {
        dim3 grid(NACT / 32, MTOT / 128);
        gemm_head<<<grid, 256>>>(p_a2, Wo, bo, out_action, MTOT, NACT, Hh, amin, amax);
    }
    (void)in_sizes; (void)n_in; (void)out_size;
}